// round 16
// baseline (speedup 1.0000x reference)
#include <cuda_runtime.h>
#include <math.h>
#include <stdint.h>

#define Bn   128
#define Dd   512
#define Tt   33
#define Ll   32
#define Vv   10000
#define G4   2048

// ---------------- static device scratch ------------------------------------
__device__ float    g_X  [Tt * Bn * Dd];        // per-step inputs
__device__ float    g_Gx [2 * Tt * Bn * G4];    // x-side gates (both layers)
__device__ float    g_H  [Ll * Bn * Dd];        // normalized h history
__device__ float    g_h  [Bn * Dd];             // carried h (normalized)
__device__ float    g_hm [Bn * Dd];             // h after layer 0
__device__ float    g_hr [Bn * Dd];             // h after layer 1 (pre-LN)
__device__ __align__(128) unsigned g_bar0;      // group-0 barrier counter
__device__ __align__(128) unsigned g_bar1;      // group-1 barrier counter (own line)
__device__ int      g_cap64;

// ---------------- utility kernels -------------------------------------------
__global__ void k_init() {
    int i = blockIdx.x * blockDim.x + threadIdx.x;
    if (i < Bn * Dd) g_h[i] = 0.f;
    if (i == 0) { g_bar0 = 0u; g_bar1 = 0u; }
}

// caption int64 vs int32 detection (values < 10000 => int64 high words all 0)
__global__ void k_detect(const int* __restrict__ cap) {
    int any = 0;
    for (int i = threadIdx.x; i < 2048; i += blockDim.x)
        if (cap[2 * i + 1] != 0) any = 1;
    any = __syncthreads_or(any);
    if (threadIdx.x == 0) g_cap64 = any ? 0 : 1;
}

__global__ void k_build_x(const float* __restrict__ features,
                          const void*  __restrict__ cap,
                          const float* __restrict__ embW) {
    int blk = blockIdx.x;
    int t = blk >> 7;
    int b = blk & 127;
    const float* src;
    if (t == 0) {
        src = features + (size_t)b * Dd;
    } else {
        long long idx;
        if (g_cap64) idx = ((const long long*)cap)[b * Ll + (t - 1)];
        else         idx = (long long)((const int*)cap)[b * Ll + (t - 1)];
        src = embW + (size_t)idx * Dd;
    }
    float4*       dst = (float4*)(g_X + ((size_t)t * Bn + b) * Dd);
    const float4* s4  = (const float4*)src;
    dst[threadIdx.x] = s4[threadIdx.x];
}

// ---------------- tf32 helpers (FC path) -------------------------------------
__device__ __forceinline__ unsigned f2t(float x) {
    unsigned r;
    asm("cvt.rna.tf32.f32 %0, %1;" : "=r"(r) : "f"(x));
    return r;
}

__device__ __forceinline__ void mma_tf32(float* c, const unsigned* a, const unsigned* b) {
    asm volatile(
        "mma.sync.aligned.m16n8k8.row.col.f32.tf32.tf32.f32 "
        "{%0,%1,%2,%3}, {%4,%5,%6,%7}, {%8,%9}, {%0,%1,%2,%3};\n"
        : "+f"(c[0]), "+f"(c[1]), "+f"(c[2]), "+f"(c[3])
        : "r"(a[0]), "r"(a[1]), "r"(a[2]), "r"(a[3]), "r"(b[0]), "r"(b[1]));
}

// ---------------- bf16 helpers -------------------------------------------------
// pack: e0 -> low half, e1 -> high half
__device__ __forceinline__ unsigned bpack(float e0, float e1) {
    unsigned r;
    asm("cvt.rn.bf16x2.f32 %0, %1, %2;" : "=r"(r) : "f"(e1), "f"(e0));
    return r;
}
__device__ __forceinline__ float blo(unsigned p) { return __uint_as_float(p << 16); }
__device__ __forceinline__ float bhi(unsigned p) { return __uint_as_float(p & 0xffff0000u); }

__device__ __forceinline__ void mma_bf16(float* c,
                                         unsigned a0, unsigned a1, unsigned a2, unsigned a3,
                                         unsigned b0, unsigned b1) {
    asm volatile(
        "mma.sync.aligned.m16n8k16.row.col.f32.bf16.bf16.f32 "
        "{%0,%1,%2,%3}, {%4,%5,%6,%7}, {%8,%9}, {%0,%1,%2,%3};\n"
        : "+f"(c[0]), "+f"(c[1]), "+f"(c[2]), "+f"(c[3])
        : "r"(a0), "r"(a1), "r"(a2), "r"(a3), "r"(b0), "r"(b1));
}

__device__ __forceinline__ void ldsm4(unsigned& r0, unsigned& r1,
                                      unsigned& r2, unsigned& r3, unsigned addr) {
    asm volatile("ldmatrix.sync.aligned.m8n8.x4.shared.b16 {%0,%1,%2,%3}, [%4];"
                 : "=r"(r0), "=r"(r1), "=r"(r2), "=r"(r3) : "r"(addr));
}

// ---------------- fast activations (saturation-safe) -------------------------
__device__ __forceinline__ float fsig(float x) {
    float e = __expf(-x);
    return __fdividef(1.f, 1.f + e);
}
__device__ __forceinline__ float ftanh(float x) {
    float e = __expf(2.f * x);
    return 1.f - __fdividef(2.f, e + 1.f);
}

// ---------------- fence-free per-group grid barrier (64 arrivals) ------------
__device__ __forceinline__ void grid_barrier(unsigned* bar, unsigned& target) {
    __syncthreads();
    if (threadIdx.x == 0) {
        target += 64u;
        asm volatile("red.release.gpu.global.add.u32 [%0], 1;" :: "l"(bar) : "memory");
        unsigned v;
        do {
            asm volatile("ld.acquire.gpu.global.u32 %0, [%1];" : "=r"(v) : "l"(bar) : "memory");
        } while (v < target);
    }
    __syncthreads();
}

// ---------------- persistent recurrence kernel (R12/R14, untouched) ----------
#define SM_BHI  0
#define SM_BLO  66560
#define SM_AHI  133120
#define SM_ALO  166912
#define SM_CS   133120
#define SM_CSM  200704
#define SM_RED  202752
#define SMEM_REC 202784
#define A_STRIDE 528            // bytes per A row (264 bf16)
#define B_STRIDE 1040           // bytes per B row (520 bf16)
#define B_LAYER  (32 * B_STRIDE)

__global__ void __launch_bounds__(256, 1)
k_recurrence(const float* __restrict__ Whh,
             const float* __restrict__ lng, const float* __restrict__ lnb) {
    extern __shared__ __align__(16) char sbuf[];
    const unsigned sbase = (unsigned)__cvta_generic_to_shared(sbuf);
    float (*Cs)[36]  = (float(*)[36])(sbuf + SM_CS);
    float (*csm)[8]  = (float(*)[8])(sbuf + SM_CSM);
    float* red       = (float*)(sbuf + SM_RED);

    const int tid  = threadIdx.x;
    const int lane = tid & 31;
    const int warp = tid >> 5;
    const int t4   = lane & 3;
    const int gid  = lane >> 2;
    const int cta  = blockIdx.x;             // 0..127
    const int jcta = cta & 63;               // j-group: cols [jcta*8, jcta*8+8)
    const int grp  = cta >> 6;               // batch group 0/1
    const int bm0  = grp * 64;               // batch-group base row
    const int wm   = warp >> 1, wn = warp & 1;  // 4x2 warps, warp tile 16x16
    unsigned* mybar = grp ? &g_bar1 : &g_bar0;
    unsigned target = 0;

    // ---- one-time: Whh slice (both layers) -> bf16 hi/lo in smem ----------
    for (int idx = tid; idx < 2 * 32 * 256; idx += 256) {
        int l  = idx >> 13;
        int rm = idx & 8191;
        int rl = rm >> 8;                    // local row 0..31
        int kp = rm & 255;                   // k-pair 0..255
        int p  = jcta * 32 + rl;
        int orig = ((p & 3) << 9) | (p >> 2);
        float2 v = *(const float2*)(Whh + ((size_t)l * G4 + orig) * Dd + kp * 2);
        unsigned h  = bpack(v.x, v.y);
        unsigned lo = bpack(v.x - blo(h), v.y - bhi(h));
        size_t roff = (size_t)(l * 32 + rl) * B_STRIDE + kp * 4;
        *(unsigned*)(sbuf + SM_BHI + roff) = h;
        *(unsigned*)(sbuf + SM_BLO + roff) = lo;
    }
    for (int i = tid; i < 64 * 8; i += 256) csm[i >> 3][i & 7] = 0.f;
    float lg0 = lng[tid], lg1 = lng[tid + 256];
    float lb0 = lnb[tid], lb1 = lnb[tid + 256];
    __syncthreads();

    // ---- ldmatrix lane address bases (constant across phases) -------------
    const int sel = lane >> 3, lr = lane & 7;
    const unsigned aHiBase = sbase + SM_AHI
        + (unsigned)((wm * 16 + (sel & 1) * 8 + lr) * A_STRIDE + (sel >> 1) * 16);
    const unsigned aLoBase = aHiBase + (SM_ALO - SM_AHI);
    const unsigned bLaneOff =
        (unsigned)((wn * 16 + (sel >> 1) * 8 + lr) * B_STRIDE + (sel & 1) * 16);

    float gpre[2][4];
#define GXLOAD(TT, LL)                                                    \
    {                                                                     \
        const float* gxp = g_Gx + ((size_t)(LL) * Tt + (TT)) * Bn * G4;   \
        _Pragma("unroll")                                                 \
        for (int it = 0; it < 2; it++) {                                  \
            int x = tid + it * 256;                                       \
            int b = bm0 + (x >> 3);                                       \
            int j = jcta * 8 + (x & 7);                                   \
            gpre[it][0] = __ldg(&gxp[b * G4 + j]);                        \
            gpre[it][1] = __ldg(&gxp[b * G4 + 512 + j]);                  \
            gpre[it][2] = __ldg(&gxp[b * G4 + 1024 + j]);                 \
            gpre[it][3] = __ldg(&gxp[b * G4 + 1536 + j]);                 \
        }                                                                 \
    }

    GXLOAD(0, 0)

    for (int t = 0; t < Tt; t++) {
#pragma unroll 1
        for (int l = 0; l < 2; l++) {
            const float* A    = (l == 0) ? g_h : g_hm;
            float*       hout = (l == 0) ? g_hm : g_hr;
            const unsigned bHiP = sbase + SM_BHI + l * B_LAYER + bLaneOff;
            const unsigned bLoP = bHiP + (SM_BLO - SM_BHI);

            float accA[2][4], accB[2][4];
#pragma unroll
            for (int n = 0; n < 2; n++)
#pragma unroll
                for (int q = 0; q < 4; q++) { accA[n][q] = 0.f; accB[n][q] = 0.f; }

#pragma unroll 1
            for (int half = 0; half < 2; half++) {
                // ---- stage A half: 64 rows x 256 k -> bf16 hi/lo ----
                const float* Ag = A + (size_t)bm0 * Dd + half * 256;
#pragma unroll
                for (int r = 0; r < 16; r++) {
                    int idx = tid + r * 256;
                    int row = idx >> 6, c4 = idx & 63;
                    float4 v = __ldcg((const float4*)(Ag + (size_t)row * Dd + c4 * 4));
                    unsigned h01 = bpack(v.x, v.y);
                    unsigned h23 = bpack(v.z, v.w);
                    unsigned l01 = bpack(v.x - blo(h01), v.y - bhi(h01));
                    unsigned l23 = bpack(v.z - blo(h23), v.w - bhi(h23));
                    size_t off = (size_t)row * A_STRIDE + c4 * 8;
                    *(uint2*)(sbuf + SM_AHI + off) = make_uint2(h01, h23);
                    *(uint2*)(sbuf + SM_ALO + off) = make_uint2(l01, l23);
                }
                __syncthreads();

                const unsigned bOff = half * 512;   // k bytes into B rows
#pragma unroll
                for (int i = 0; i < 16; i++) {
                    unsigned ah0, ah1, ah2, ah3, al0, al1, al2, al3;
                    unsigned bh0, bh1, bh2, bh3, bl0, bl1, bl2, bl3;
                    ldsm4(ah0, ah1, ah2, ah3, aHiBase + i * 32);
                    ldsm4(al0, al1, al2, al3, aLoBase + i * 32);
                    ldsm4(bh0, bh1, bh2, bh3, bHiP + bOff + i * 32);
                    ldsm4(bl0, bl1, bl2, bl3, bLoP + bOff + i * 32);
                    mma_bf16(accA[0], ah0, ah1, ah2, ah3, bh0, bh1);  // hi.hi n0
                    mma_bf16(accB[0], al0, al1, al2, al3, bh0, bh1);  // lo.hi n0
                    mma_bf16(accB[0], ah0, ah1, ah2, ah3, bl0, bl1);  // hi.lo n0
                    mma_bf16(accA[1], ah0, ah1, ah2, ah3, bh2, bh3);  // hi.hi n1
                    mma_bf16(accB[1], al0, al1, al2, al3, bh2, bh3);  // lo.hi n1
                    mma_bf16(accB[1], ah0, ah1, ah2, ah3, bl2, bl3);  // hi.lo n1
                }
                __syncthreads();
            }
            // accumulators -> Cs (unions A staging; safe after sync)
#pragma unroll
            for (int nf = 0; nf < 2; nf++) {
                int r0 = wm * 16 + gid;
                int c0 = wn * 16 + nf * 8 + 2 * t4;
                Cs[r0    ][c0    ] = accA[nf][0] + accB[nf][0];
                Cs[r0    ][c0 + 1] = accA[nf][1] + accB[nf][1];
                Cs[r0 + 8][c0    ] = accA[nf][2] + accB[nf][2];
                Cs[r0 + 8][c0 + 1] = accA[nf][3] + accB[nf][3];
            }
            __syncthreads();
            // LSTM cell: 64x8 = 512 elements, 2 per thread (gx preloaded)
#pragma unroll
            for (int it = 0; it < 2; it++) {
                int x    = tid + it * 256;
                int brow = x >> 3, jj = x & 7;
                int b    = bm0 + brow;
                int j    = jcta * 8 + jj;
                float gi = Cs[brow][jj * 4 + 0] + gpre[it][0];
                float gf = Cs[brow][jj * 4 + 1] + gpre[it][1];
                float gg = Cs[brow][jj * 4 + 2] + gpre[it][2];
                float go = Cs[brow][jj * 4 + 3] + gpre[it][3];
                float ii = fsig(gi);
                float ff = fsig(gf);
                float gt = ftanh(gg);
                float oo = fsig(go);
                float cn = ff * csm[brow][jj] + ii * gt;
                csm[brow][jj] = cn;
                __stcg(&hout[(size_t)b * Dd + j], oo * ftanh(cn));
            }
            // hoist next phase's gx loads across the barrier (static data)
            if (l == 0) { GXLOAD(t, 1) }
            else if (t + 1 < Tt) { GXLOAD(t + 1, 0) }
            grid_barrier(mybar, target);
        }
        // ---- LayerNorm: CTA handles batch row b = cta (256 threads, 2 elems) --
        {
            const float* xr = g_hr + (size_t)cta * Dd;
            float v0 = __ldcg(&xr[tid]), v1 = __ldcg(&xr[tid + 256]);
            float s = v0 + v1;
#pragma unroll
            for (int o = 16; o > 0; o >>= 1) s += __shfl_xor_sync(0xffffffffu, s, o);
            if (lane == 0) red[warp] = s;
            __syncthreads();
            float mu = (red[0] + red[1] + red[2] + red[3] +
                        red[4] + red[5] + red[6] + red[7]) * (1.f / 512.f);
            __syncthreads();
            float d0 = v0 - mu, d1 = v1 - mu;
            float vv = d0 * d0 + d1 * d1;
#pragma unroll
            for (int o = 16; o > 0; o >>= 1) vv += __shfl_xor_sync(0xffffffffu, vv, o);
            if (lane == 0) red[warp] = vv;
            __syncthreads();
            float var  = (red[0] + red[1] + red[2] + red[3] +
                          red[4] + red[5] + red[6] + red[7]) * (1.f / 512.f);
            float rstd = rsqrtf(var + 1e-5f);
            float y0 = d0 * rstd * lg0 + lb0;
            float y1 = d1 * rstd * lg1 + lb1;
            __stcg(&g_h[(size_t)cta * Dd + tid],       y0);
            __stcg(&g_h[(size_t)cta * Dd + tid + 256], y1);
            if (t > 0) {
                g_H[((size_t)(t - 1) * Bn + cta) * Dd + tid]       = y0;
                g_H[((size_t)(t - 1) * Bn + cta) * Dd + tid + 256] = y1;
            }
            __syncthreads();
        }
        grid_barrier(mybar, target);
    }
#undef GXLOAD
}

// ---------------- Gx GEMM, bf16x3 + ldmatrix + DOUBLE BUFFER ------------------
// BM=128, BN=64, K-tile 16, 256 threads, 4(m)x2(n) warps, warp tile 32x32.
// 2 smem buffers (18432 B each) -> ONE sync per k-tile; STS overlaps mma.
#define GXA_HI 0
#define GXA_LO 6144
#define GXB_HI 12288
#define GXB_LO 15360
#define GX_STR 48
#define GX_BUF 18432
__global__ void __launch_bounds__(256)
gemm_gx_bf16(const float* __restrict__ A, int M, int lda,
             const float* __restrict__ Bm, int N, int ldb, int K,
             const float* __restrict__ bias1, const float* __restrict__ bias2,
             float* __restrict__ C, int ldc)
{
    __shared__ __align__(16) char gs[2 * GX_BUF];
    const unsigned sb = (unsigned)__cvta_generic_to_shared(gs);

    const int tid  = threadIdx.x;
    const int lane = tid & 31;
    const int warp = tid >> 5;
    const int wn = warp & 1, wm = warp >> 1;   // 4x2 warps
    const int gid = lane >> 2, t4 = lane & 3;
    const int m0 = blockIdx.x * 128;
    const int n0 = blockIdx.y * 64;

    float acc[2][4][4];
#pragma unroll
    for (int i = 0; i < 2; i++)
#pragma unroll
        for (int j = 0; j < 4; j++)
#pragma unroll
            for (int q = 0; q < 4; q++) acc[i][j][q] = 0.f;

    float4 ra[2], rb;
    const int arow = tid >> 2, acb = tid & 3;
#define LOAD_T(K0)                                                           \
    {                                                                        \
        ra[0] = *(const float4*)(A + (size_t)(m0 + arow) * lda + (K0) + acb * 4);       \
        ra[1] = *(const float4*)(A + (size_t)(m0 + arow + 64) * lda + (K0) + acb * 4);  \
        rb    = *(const float4*)(Bm + (size_t)(n0 + arow) * ldb + (K0) + acb * 4);      \
    }
#define CVT_STORE(BUF)                                                       \
    {                                                                        \
        char* gp = gs + (BUF) * GX_BUF;                                      \
        _Pragma("unroll")                                                    \
        for (int i = 0; i < 2; i++) {                                        \
            unsigned h01 = bpack(ra[i].x, ra[i].y);                          \
            unsigned h23 = bpack(ra[i].z, ra[i].w);                          \
            unsigned l01 = bpack(ra[i].x - blo(h01), ra[i].y - bhi(h01));    \
            unsigned l23 = bpack(ra[i].z - blo(h23), ra[i].w - bhi(h23));    \
            unsigned off = (arow + i * 64) * GX_STR + acb * 8;               \
            *(uint2*)(gp + GXA_HI + off) = make_uint2(h01, h23);             \
            *(uint2*)(gp + GXA_LO + off) = make_uint2(l01, l23);             \
        }                                                                    \
        {                                                                    \
            unsigned h01 = bpack(rb.x, rb.y);                                \
            unsigned h23 = bpack(rb.z, rb.w);                                \
            unsigned l01 = bpack(rb.x - blo(h01), rb.y - bhi(h01));          \
            unsigned l23 = bpack(rb.z - blo(h23), rb.w - bhi(h23));          \
            unsigned off = arow * GX_STR + acb * 8;                          \
            *(uint2*)(gp + GXB_HI + off) = make_uint2(h01, h23);             \
            *(uint2*)(gp + GXB_LO + off) = make_uint2(l01, l23);             \
        }                                                                    \
    }

    const int sel = lane >> 3, lr = lane & 7;
    const unsigned aBase = sb + GXA_HI
        + (unsigned)((wm * 32 + (sel & 1) * 8 + lr) * GX_STR + (sel >> 1) * 16);
    const unsigned bBase = sb + GXB_HI
        + (unsigned)((wn * 32 + (sel >> 1) * 8 + lr) * GX_STR + (sel & 1) * 16);

    // prologue: fill buffer 0, prefetch k-tile 1
    LOAD_T(0)
    CVT_STORE(0)
    LOAD_T(16)
    __syncthreads();

    const int NT = K / 16;      // 32 k-tiles
#pragma unroll 1
    for (int it = 0; it < NT; it++) {
        const unsigned bufo = (unsigned)(it & 1) * GX_BUF;

        unsigned bhf[2][4], blf[2][4];
#pragma unroll
        for (int nf2 = 0; nf2 < 2; nf2++) {
            ldsm4(bhf[nf2][0], bhf[nf2][1], bhf[nf2][2], bhf[nf2][3],
                  bBase + bufo + nf2 * 16 * GX_STR);
            ldsm4(blf[nf2][0], blf[nf2][1], blf[nf2][2], blf[nf2][3],
                  bBase + bufo + (GXB_LO - GXB_HI) + nf2 * 16 * GX_STR);
        }
#pragma unroll
        for (int mf = 0; mf < 2; mf++) {
            unsigned ah0, ah1, ah2, ah3, al0, al1, al2, al3;
            ldsm4(ah0, ah1, ah2, ah3, aBase + bufo + mf * 16 * GX_STR);
            ldsm4(al0, al1, al2, al3, aBase + bufo + (GXA_LO - GXA_HI) + mf * 16 * GX_STR);
#pragma unroll
            for (int nf2 = 0; nf2 < 2; nf2++) {
                mma_bf16(acc[mf][nf2 * 2    ], ah0, ah1, ah2, ah3, bhf[nf2][0], bhf[nf2][1]);
                mma_bf16(acc[mf][nf2 * 2    ], al0, al1, al2, al3, bhf[nf2][0], bhf[nf2][1]);
                mma_bf16(acc[mf][nf2 * 2    ], ah0, ah1, ah2, ah3, blf[nf2][0], blf[nf2][1]);
                mma_bf16(acc[mf][nf2 * 2 + 1], ah0, ah1, ah2, ah3, bhf[nf2][2], bhf[nf2][3]);
                mma_bf16(acc[mf][nf2 * 2 + 1], al0, al1, al2, al3, bhf[nf2][2], bhf[nf2][3]);
                mma_bf16(acc[mf][nf2 * 2 + 1], ah0, ah1, ah2, ah3, blf[nf2][2], blf[nf2][3]);
            }
        }
        if (it < NT - 1) {
            CVT_STORE((it + 1) & 1)            // regs from last prefetch
            if (it < NT - 2) LOAD_T((it + 2) * 16)
        }
        __syncthreads();
    }

#pragma unroll
    for (int mf = 0; mf < 2; mf++)
#pragma unroll
        for (int nf = 0; nf < 4; nf++) {
            int r0 = m0 + wm * 32 + mf * 16 + gid;
            int c0 = n0 + wn * 32 + nf * 8 + 2 * t4;
#pragma unroll
            for (int q = 0; q < 4; q++) {
                int r = r0 + ((q >= 2) ? 8 : 0);
                int c = c0 + (q & 1);
                C[(size_t)r * ldc + c] = acc[mf][nf][q] + bias1[c] + bias2[c];
            }
        }
#undef LOAD_T
#undef CVT_STORE
}

// ---------------- FC GEMM (tf32, PAD=8) + DOUBLE BUFFER -----------------------
template<int BM, int BN, int WM, int WN>
__global__ void __launch_bounds__(WM * WN * 32)
gemm_fc(const float* __restrict__ A, int M, int lda,
        const float* __restrict__ Bm, int N, int ldb, int K,
        const float* __restrict__ bias1,
        float* __restrict__ C, int ldc)
{
    constexpr int THREADS = WM * WN * 32;
    constexpr int PAD = 8;
    constexpr int MF = 2, NF = 4;

    __shared__ unsigned Ash[2][16][BM + PAD];
    __shared__ unsigned Bsh[2][16][BN + PAD];

    const int tid  = threadIdx.x;
    const int lane = tid & 31;
    const int warp = tid >> 5;
    const int wn = warp % WN, wm = warp / WN;
    const int gid = lane >> 2, t4 = lane & 3;
    const int m0 = blockIdx.x * BM;
    const int n0 = blockIdx.y * BN;

    float acc[MF][NF][4];
#pragma unroll
    for (int i = 0; i < MF; i++)
#pragma unroll
        for (int j = 0; j < NF; j++)
#pragma unroll
            for (int q = 0; q < 4; q++) acc[i][j][q] = 0.f;

    constexpr int LA = (BM * 16) / (THREADS * 4);
    constexpr int LB = (BN * 16) / (THREADS * 4);

    float4 ra[LA], rb[LB];

#define LOAD_T(K0)                                                          \
    {                                                                       \
        _Pragma("unroll")                                                   \
        for (int i = 0; i < LA; i++) {                                      \
            int f4 = tid + i * THREADS;                                     \
            int row = f4 >> 2, cb = f4 & 3;                                 \
            int gm = m0 + row;                                              \
            ra[i] = make_float4(0.f, 0.f, 0.f, 0.f);                        \
            if (gm < M) ra[i] = *(const float4*)(A + (size_t)gm * lda + (K0) + cb * 4); \
        }                                                                   \
        _Pragma("unroll")                                                   \
        for (int i = 0; i < LB; i++) {                                      \
            int f4 = tid + i * THREADS;                                     \
            int row = f4 >> 2, cb = f4 & 3;                                 \
            int grow = n0 + row;                                            \
            rb[i] = make_float4(0.f, 0.f, 0.f, 0.f);                        \
            if (grow < N) rb[i] = *(const float4*)(Bm + (size_t)grow * ldb + (K0) + cb * 4); \
        }                                                                   \
    }
#define CVT_STORE(BUF)                                                      \
    {                                                                       \
        _Pragma("unroll")                                                   \
        for (int i = 0; i < LA; i++) {                                      \
            int f4 = tid + i * THREADS;                                     \
            int row = f4 >> 2, cb = f4 & 3;                                 \
            Ash[BUF][cb * 4 + 0][row] = f2t(ra[i].x);                       \
            Ash[BUF][cb * 4 + 1][row] = f2t(ra[i].y);                       \
            Ash[BUF][cb * 4 + 2][row] = f2t(ra[i].z);                       \
            Ash[BUF][cb * 4 + 3][row] = f2t(ra[i].w);                       \
        }                                                                   \
        _Pragma("unroll")                                                   \
        for (int i = 0; i < LB; i++) {                                      \
            int f4 = tid + i * THREADS;                                     \
            int row = f4 >> 2, cb = f4 & 3;                                 \
            Bsh[BUF][cb * 4 + 0][row] = f2t(rb[i].x);                       \
            Bsh[BUF][cb * 4 + 1][row] = f2t(rb[i].y);                       \
            Bsh[BUF][cb * 4 + 2][row] = f2t(rb[i].z);                       \
            Bsh[BUF][cb * 4 + 3][row] = f2t(rb[i].w);                       \
        }                                                                   \
    }

    LOAD_T(0)
    CVT_STORE(0)
    LOAD_T(16)
    __syncthreads();

    const int NT = K / 16;
#pragma unroll 1
    for (int it = 0; it < NT; it++) {
        const int cur = it & 1;
#pragma unroll
        for (int ks = 0; ks < 2; ks++) {
            const int kb = ks * 8;
            unsigned ah[MF][4], bh[NF][2];
#pragma unroll
            for (int mf = 0; mf < MF; mf++) {
                int mm = wm * 32 + mf * 16 + gid;
                ah[mf][0] = Ash[cur][kb + t4    ][mm];
                ah[mf][1] = Ash[cur][kb + t4    ][mm + 8];
                ah[mf][2] = Ash[cur][kb + t4 + 4][mm];
                ah[mf][3] = Ash[cur][kb + t4 + 4][mm + 8];
            }
#pragma unroll
            for (int nf = 0; nf < NF; nf++) {
                int nn = wn * 32 + nf * 8 + gid;
                bh[nf][0] = Bsh[cur][kb + t4    ][nn];
                bh[nf][1] = Bsh[cur][kb + t4 + 4][nn];
            }
#pragma unroll
            for (int mf = 0; mf < MF; mf++)
#pragma unroll
                for (int nf = 0; nf < NF; nf++)
                    mma_tf32(acc[mf][nf], ah[mf], bh[nf]);
        }
        if (it < NT - 1) {
            CVT_STORE(cur ^ 1)
            if (it < NT - 2) LOAD_T((it + 2) * 16)
        }
        __syncthreads();
    }

#pragma unroll
    for (int mf = 0; mf < MF; mf++)
#pragma unroll
        for (int nf = 0; nf < NF; nf++) {
            int r0 = m0 + wm * 32 + mf * 16 + gid;
            int c0 = n0 + wn * 32 + nf * 8 + 2 * t4;
#pragma unroll
            for (int q = 0; q < 4; q++) {
                int r = r0 + ((q >= 2) ? 8 : 0);
                int c = c0 + (q & 1);
                if (r < M && c < N) {
                    int orow = (r & 127) * Ll + (r >> 7);
                    C[(size_t)orow * ldc + c] = acc[mf][nf][q] + bias1[c];
                }
            }
        }
#undef LOAD_T
#undef CVT_STORE
}

// ---------------- in-place log_softmax, rows of 10000, 512 threads -----------
__global__ void k_lsm(float* __restrict__ out) {
    __shared__ float row[Vv];
    __shared__ float red[16];
    float* p = out + (size_t)blockIdx.x * Vv;
    int tid = threadIdx.x;            // 512 threads

    float mx = -1e30f;
    float4*       r4 = (float4*)row;
    const float4* p4 = (const float4*)p;
    for (int i = tid; i < Vv / 4; i += 512) {
        float4 v = p4[i];
        r4[i] = v;
        mx = fmaxf(mx, fmaxf(fmaxf(v.x, v.y), fmaxf(v.z, v.w)));
    }
#pragma unroll
    for (int o = 16; o > 0; o >>= 1) mx = fmaxf(mx, __shfl_xor_sync(0xffffffffu, mx, o));
    if ((tid & 31) == 0) red[tid >> 5] = mx;
    __syncthreads();
    mx = red[0];
#pragma unroll
    for (int i = 1; i < 16; i++) mx = fmaxf(mx, red[i]);

    float s = 0.f;
    for (int i = tid; i < Vv; i += 512) s += expf(row[i] - mx);
#pragma unroll
    for (int o = 16; o > 0; o >>= 1) s += __shfl_xor_sync(0xffffffffu, s, o);
    __syncthreads();
    if ((tid & 31) == 0) red[tid >> 5] = s;
    __syncthreads();
    s = 0.f;
#pragma unroll
    for (int i = 0; i < 16; i++) s += red[i];
    float lse = mx + logf(s);

    for (int i = tid; i < Vv; i += 512) p[i] = row[i] - lse;
}

// ---------------- host launcher ----------------------------------------------
extern "C" void kernel_launch(void* const* d_in, const int* in_sizes, int n_in,
                              void* d_out, int out_size) {
    const float* features = (const float*)d_in[0];
    const void*  caption  = d_in[1];
    const float* embW     = (const float*)d_in[2];
    const float* Wih      = (const float*)d_in[3];
    const float* Whh      = (const float*)d_in[4];
    const float* bih      = (const float*)d_in[5];
    const float* bhh      = (const float*)d_in[6];
    const float* lng      = (const float*)d_in[7];
    const float* lnb      = (const float*)d_in[8];
    const float* fcW      = (const float*)d_in[9];
    const float* fcb      = (const float*)d_in[10];
    float*       out      = (float*)d_out;

    float *pX, *pGx, *pH;
    cudaGetSymbolAddress((void**)&pX,  g_X);
    cudaGetSymbolAddress((void**)&pGx, g_Gx);
    cudaGetSymbolAddress((void**)&pH,  g_H);

    cudaFuncSetAttribute(k_recurrence,
                         cudaFuncAttributeMaxDynamicSharedMemorySize, SMEM_REC);

    k_init<<<256, 256>>>();
    k_detect<<<1, 256>>>((const int*)caption);
    k_build_x<<<Tt * Bn, 128>>>(features, caption, embW);

    // Gx = X @ Wih^T + bih + bhh   (both layers, bf16x3 + ldmatrix, dbl-buf)
    for (int l = 0; l < 2; l++)
        gemm_gx_bf16<<<dim3(33, 32), 256>>>(
            pX, Tt * Bn, Dd,
            Wih + (size_t)l * G4 * Dd, G4, Dd, Dd,
            bih + l * G4, bhh + l * G4,
            pGx + (size_t)l * Tt * Bn * G4, G4);

    // full 33-step recurrence in ONE persistent kernel (single wave)
    k_recurrence<<<128, 256, SMEM_REC>>>(Whh, lng, lnb);

    // FC: logits = H @ fcW^T + fcb  (single tf32, permuted store, dbl-buf)
    gemm_fc<128, 64, 4, 2><<<dim3(32, 157), 256>>>(
        pH, Ll * Bn, Dd, fcW, Vv, Dd, Dd,
        fcb, out, Vv);

    k_lsm<<<Ll * Bn, 512>>>(out);
}

// round 17
// speedup vs baseline: 1.0119x; 1.0119x over previous
#include <cuda_runtime.h>
#include <math.h>
#include <stdint.h>

#define Bn   128
#define Dd   512
#define Tt   33
#define Ll   32
#define Vv   10000
#define G4   2048

// ---------------- static device scratch ------------------------------------
__device__ float    g_X  [Tt * Bn * Dd];        // per-step inputs
__device__ float    g_Gx [2 * Tt * Bn * G4];    // x-side gates (both layers)
__device__ float    g_H  [Ll * Bn * Dd];        // normalized h history
__device__ float    g_h  [Bn * Dd];             // carried h (normalized)
__device__ float    g_hm [Bn * Dd];             // h after layer 0
__device__ float    g_hr [Bn * Dd];             // h after layer 1 (pre-LN)
__device__ __align__(128) unsigned g_bar0;      // group-0 barrier counter
__device__ __align__(128) unsigned g_bar1;      // group-1 barrier counter (own line)
__device__ int      g_cap64;

// ---------------- utility kernels -------------------------------------------
__global__ void k_init() {
    int i = blockIdx.x * blockDim.x + threadIdx.x;
    if (i < Bn * Dd) g_h[i] = 0.f;
    if (i == 0) { g_bar0 = 0u; g_bar1 = 0u; }
}

// caption int64 vs int32 detection (values < 10000 => int64 high words all 0)
__global__ void k_detect(const int* __restrict__ cap) {
    int any = 0;
    for (int i = threadIdx.x; i < 2048; i += blockDim.x)
        if (cap[2 * i + 1] != 0) any = 1;
    any = __syncthreads_or(any);
    if (threadIdx.x == 0) g_cap64 = any ? 0 : 1;
}

__global__ void k_build_x(const float* __restrict__ features,
                          const void*  __restrict__ cap,
                          const float* __restrict__ embW) {
    int blk = blockIdx.x;
    int t = blk >> 7;
    int b = blk & 127;
    const float* src;
    if (t == 0) {
        src = features + (size_t)b * Dd;
    } else {
        long long idx;
        if (g_cap64) idx = ((const long long*)cap)[b * Ll + (t - 1)];
        else         idx = (long long)((const int*)cap)[b * Ll + (t - 1)];
        src = embW + (size_t)idx * Dd;
    }
    float4*       dst = (float4*)(g_X + ((size_t)t * Bn + b) * Dd);
    const float4* s4  = (const float4*)src;
    dst[threadIdx.x] = s4[threadIdx.x];
}

// ---------------- tf32 helpers (FC path) -------------------------------------
__device__ __forceinline__ unsigned f2t(float x) {
    unsigned r;
    asm("cvt.rna.tf32.f32 %0, %1;" : "=r"(r) : "f"(x));
    return r;
}

__device__ __forceinline__ void mma_tf32(float* c, const unsigned* a, const unsigned* b) {
    asm volatile(
        "mma.sync.aligned.m16n8k8.row.col.f32.tf32.tf32.f32 "
        "{%0,%1,%2,%3}, {%4,%5,%6,%7}, {%8,%9}, {%0,%1,%2,%3};\n"
        : "+f"(c[0]), "+f"(c[1]), "+f"(c[2]), "+f"(c[3])
        : "r"(a[0]), "r"(a[1]), "r"(a[2]), "r"(a[3]), "r"(b[0]), "r"(b[1]));
}

// ---------------- bf16 helpers -------------------------------------------------
// pack: e0 -> low half, e1 -> high half
__device__ __forceinline__ unsigned bpack(float e0, float e1) {
    unsigned r;
    asm("cvt.rn.bf16x2.f32 %0, %1, %2;" : "=r"(r) : "f"(e1), "f"(e0));
    return r;
}
__device__ __forceinline__ float blo(unsigned p) { return __uint_as_float(p << 16); }
__device__ __forceinline__ float bhi(unsigned p) { return __uint_as_float(p & 0xffff0000u); }

__device__ __forceinline__ void mma_bf16(float* c,
                                         unsigned a0, unsigned a1, unsigned a2, unsigned a3,
                                         unsigned b0, unsigned b1) {
    asm volatile(
        "mma.sync.aligned.m16n8k16.row.col.f32.bf16.bf16.f32 "
        "{%0,%1,%2,%3}, {%4,%5,%6,%7}, {%8,%9}, {%0,%1,%2,%3};\n"
        : "+f"(c[0]), "+f"(c[1]), "+f"(c[2]), "+f"(c[3])
        : "r"(a0), "r"(a1), "r"(a2), "r"(a3), "r"(b0), "r"(b1));
}

__device__ __forceinline__ void ldsm4(unsigned& r0, unsigned& r1,
                                      unsigned& r2, unsigned& r3, unsigned addr) {
    asm volatile("ldmatrix.sync.aligned.m8n8.x4.shared.b16 {%0,%1,%2,%3}, [%4];"
                 : "=r"(r0), "=r"(r1), "=r"(r2), "=r"(r3) : "r"(addr));
}

// ---------------- fast activations (saturation-safe) -------------------------
__device__ __forceinline__ float fsig(float x) {
    float e = __expf(-x);
    return __fdividef(1.f, 1.f + e);
}
__device__ __forceinline__ float ftanh(float x) {
    float e = __expf(2.f * x);
    return 1.f - __fdividef(2.f, e + 1.f);
}

// ---------------- fence-free per-group grid barrier (64 arrivals) ------------
__device__ __forceinline__ void grid_barrier(unsigned* bar, unsigned& target) {
    __syncthreads();
    if (threadIdx.x == 0) {
        target += 64u;
        asm volatile("red.release.gpu.global.add.u32 [%0], 1;" :: "l"(bar) : "memory");
        unsigned v;
        do {
            asm volatile("ld.acquire.gpu.global.u32 %0, [%1];" : "=r"(v) : "l"(bar) : "memory");
        } while (v < target);
    }
    __syncthreads();
}

// ---------------- persistent recurrence kernel -------------------------------
// 128 CTAs x 256 threads = 2 independent batch-groups (64 rows) x 64 j-groups.
// Whh (both layers) in smem as bf16 hi/lo, row stride 1040 B (ldmatrix
// conflict-free). A staged in QUARTER-K chunks (64x128), double-buffered:
// LDG a quarter ahead, cvt+STS after the mma block -> staging overlapped.
#define SM_BHI  0
#define SM_BLO  66560
#define SM_AQ   133120          // 2 bufs x (hi 17408 + lo 17408) = 69632
#define AQ_SZ   17408
#define SM_CS   133120          // unions A staging (post-mma only)
#define SM_CSM  202752
#define SM_RED  204800
#define SMEM_REC 204832
#define AQ_STRIDE 272           // bytes per A row (128 bf16 + pad); %128==16
#define B_STRIDE 1040           // bytes per B row (520 bf16)
#define B_LAYER  (32 * B_STRIDE)

__global__ void __launch_bounds__(256, 1)
k_recurrence(const float* __restrict__ Whh,
             const float* __restrict__ lng, const float* __restrict__ lnb) {
    extern __shared__ __align__(16) char sbuf[];
    const unsigned sbase = (unsigned)__cvta_generic_to_shared(sbuf);
    float (*Cs)[36]  = (float(*)[36])(sbuf + SM_CS);
    float (*csm)[8]  = (float(*)[8])(sbuf + SM_CSM);
    float* red       = (float*)(sbuf + SM_RED);

    const int tid  = threadIdx.x;
    const int lane = tid & 31;
    const int warp = tid >> 5;
    const int t4   = lane & 3;
    const int gid  = lane >> 2;
    const int cta  = blockIdx.x;             // 0..127
    const int jcta = cta & 63;               // j-group: cols [jcta*8, jcta*8+8)
    const int grp  = cta >> 6;               // batch group 0/1
    const int bm0  = grp * 64;               // batch-group base row
    const int wm   = warp >> 1, wn = warp & 1;  // 4x2 warps, warp tile 16x16
    unsigned* mybar = grp ? &g_bar1 : &g_bar0;
    unsigned target = 0;

    // ---- one-time: Whh slice (both layers) -> bf16 hi/lo in smem ----------
    for (int idx = tid; idx < 2 * 32 * 256; idx += 256) {
        int l  = idx >> 13;
        int rm = idx & 8191;
        int rl = rm >> 8;                    // local row 0..31
        int kp = rm & 255;                   // k-pair 0..255
        int p  = jcta * 32 + rl;
        int orig = ((p & 3) << 9) | (p >> 2);
        float2 v = *(const float2*)(Whh + ((size_t)l * G4 + orig) * Dd + kp * 2);
        unsigned h  = bpack(v.x, v.y);
        unsigned lo = bpack(v.x - blo(h), v.y - bhi(h));
        size_t roff = (size_t)(l * 32 + rl) * B_STRIDE + kp * 4;
        *(unsigned*)(sbuf + SM_BHI + roff) = h;
        *(unsigned*)(sbuf + SM_BLO + roff) = lo;
    }
    for (int i = tid; i < 64 * 8; i += 256) csm[i >> 3][i & 7] = 0.f;
    float lg0 = lng[tid], lg1 = lng[tid + 256];
    float lb0 = lnb[tid], lb1 = lnb[tid + 256];
    __syncthreads();

    // ---- ldmatrix lane address bases -------------------------------------
    const int sel = lane >> 3, lr = lane & 7;
    const unsigned aHiBase = sbase + SM_AQ
        + (unsigned)((wm * 16 + (sel & 1) * 8 + lr) * AQ_STRIDE + (sel >> 1) * 16);
    const unsigned bLaneOff =
        (unsigned)((wn * 16 + (sel >> 1) * 8 + lr) * B_STRIDE + (sel & 1) * 16);

    // A staging copy assignment (constant)
    const int srow = tid >> 5;               // base row stepping by 8
    const int sc4  = tid & 31;               // float4 column within 128-k quarter
    (void)srow;

    float gpre[2][4];
#define GXLOAD(TT, LL)                                                    \
    {                                                                     \
        const float* gxp = g_Gx + ((size_t)(LL) * Tt + (TT)) * Bn * G4;   \
        _Pragma("unroll")                                                 \
        for (int it = 0; it < 2; it++) {                                  \
            int x = tid + it * 256;                                       \
            int b = bm0 + (x >> 3);                                       \
            int j = jcta * 8 + (x & 7);                                   \
            gpre[it][0] = __ldg(&gxp[b * G4 + j]);                        \
            gpre[it][1] = __ldg(&gxp[b * G4 + 512 + j]);                  \
            gpre[it][2] = __ldg(&gxp[b * G4 + 1024 + j]);                 \
            gpre[it][3] = __ldg(&gxp[b * G4 + 1536 + j]);                 \
        }                                                                 \
    }
#define LOADQ(Q)                                                          \
    {                                                                     \
        const float* Ag = A + (size_t)bm0 * Dd + (Q) * 128;               \
        _Pragma("unroll")                                                 \
        for (int r = 0; r < 8; r++) {                                     \
            int row = (tid >> 5) + r * 8;                                 \
            va[r] = __ldcg((const float4*)(Ag + (size_t)row * Dd + sc4 * 4)); \
        }                                                                 \
    }
#define STOREQ(B)                                                         \
    {                                                                     \
        char* bp = sbuf + SM_AQ + (B) * (2 * AQ_SZ);                      \
        _Pragma("unroll")                                                 \
        for (int r = 0; r < 8; r++) {                                     \
            int row = (tid >> 5) + r * 8;                                 \
            unsigned h01 = bpack(va[r].x, va[r].y);                       \
            unsigned h23 = bpack(va[r].z, va[r].w);                       \
            unsigned l01 = bpack(va[r].x - blo(h01), va[r].y - bhi(h01)); \
            unsigned l23 = bpack(va[r].z - blo(h23), va[r].w - bhi(h23)); \
            size_t off = (size_t)row * AQ_STRIDE + sc4 * 8;               \
            *(uint2*)(bp + off)         = make_uint2(h01, h23);           \
            *(uint2*)(bp + AQ_SZ + off) = make_uint2(l01, l23);           \
        }                                                                 \
    }

    GXLOAD(0, 0)

    for (int t = 0; t < Tt; t++) {
#pragma unroll 1
        for (int l = 0; l < 2; l++) {
            const float* A    = (l == 0) ? g_h : g_hm;
            float*       hout = (l == 0) ? g_hm : g_hr;
            const unsigned bHiP = sbase + SM_BHI + l * B_LAYER + bLaneOff;
            const unsigned bLoP = bHiP + (SM_BLO - SM_BHI);

            float accA[2][4], accB[2][4];
#pragma unroll
            for (int n = 0; n < 2; n++)
#pragma unroll
                for (int q = 0; q < 4; q++) { accA[n][q] = 0.f; accB[n][q] = 0.f; }

            float4 va[8];
            LOADQ(0)
            STOREQ(0)
            LOADQ(1)
            __syncthreads();

#pragma unroll 1
            for (int q = 0; q < 4; q++) {
                const unsigned abuf = (unsigned)(q & 1) * (2 * AQ_SZ);
                const unsigned bQ   = (unsigned)q * 256;   // 128 bf16 per quarter
#pragma unroll
                for (int i = 0; i < 8; i++) {
                    unsigned ah0, ah1, ah2, ah3, al0, al1, al2, al3;
                    unsigned bh0, bh1, bh2, bh3, bl0, bl1, bl2, bl3;
                    ldsm4(ah0, ah1, ah2, ah3, aHiBase + abuf + i * 32);
                    ldsm4(al0, al1, al2, al3, aHiBase + abuf + AQ_SZ + i * 32);
                    ldsm4(bh0, bh1, bh2, bh3, bHiP + bQ + i * 32);
                    ldsm4(bl0, bl1, bl2, bl3, bLoP + bQ + i * 32);
                    mma_bf16(accA[0], ah0, ah1, ah2, ah3, bh0, bh1);  // hi.hi n0
                    mma_bf16(accB[0], al0, al1, al2, al3, bh0, bh1);  // lo.hi n0
                    mma_bf16(accB[0], ah0, ah1, ah2, ah3, bl0, bl1);  // hi.lo n0
                    mma_bf16(accA[1], ah0, ah1, ah2, ah3, bh2, bh3);  // hi.hi n1
                    mma_bf16(accB[1], al0, al1, al2, al3, bh2, bh3);  // lo.hi n1
                    mma_bf16(accB[1], ah0, ah1, ah2, ah3, bl2, bl3);  // hi.lo n1
                }
                if (q < 3) {
                    STOREQ((q & 1) ^ 1)
                    if (q < 2) LOADQ(q + 2)
                }
                __syncthreads();
            }
            // accumulators -> Cs (unions A staging; safe after last sync)
#pragma unroll
            for (int nf = 0; nf < 2; nf++) {
                int r0 = wm * 16 + gid;
                int c0 = wn * 16 + nf * 8 + 2 * t4;
                Cs[r0    ][c0    ] = accA[nf][0] + accB[nf][0];
                Cs[r0    ][c0 + 1] = accA[nf][1] + accB[nf][1];
                Cs[r0 + 8][c0    ] = accA[nf][2] + accB[nf][2];
                Cs[r0 + 8][c0 + 1] = accA[nf][3] + accB[nf][3];
            }
            __syncthreads();
            // LSTM cell: 64x8 = 512 elements, 2 per thread (gx preloaded)
#pragma unroll
            for (int it = 0; it < 2; it++) {
                int x    = tid + it * 256;
                int brow = x >> 3, jj = x & 7;
                int b    = bm0 + brow;
                int j    = jcta * 8 + jj;
                float gi = Cs[brow][jj * 4 + 0] + gpre[it][0];
                float gf = Cs[brow][jj * 4 + 1] + gpre[it][1];
                float gg = Cs[brow][jj * 4 + 2] + gpre[it][2];
                float go = Cs[brow][jj * 4 + 3] + gpre[it][3];
                float ii = fsig(gi);
                float ff = fsig(gf);
                float gt = ftanh(gg);
                float oo = fsig(go);
                float cn = ff * csm[brow][jj] + ii * gt;
                csm[brow][jj] = cn;
                __stcg(&hout[(size_t)b * Dd + j], oo * ftanh(cn));
            }
            // hoist next phase's gx loads across the barrier (static data)
            if (l == 0) { GXLOAD(t, 1) }
            else if (t + 1 < Tt) { GXLOAD(t + 1, 0) }
            grid_barrier(mybar, target);
        }
        // ---- LayerNorm: CTA handles batch row b = cta (256 threads, 2 elems) --
        {
            const float* xr = g_hr + (size_t)cta * Dd;
            float v0 = __ldcg(&xr[tid]), v1 = __ldcg(&xr[tid + 256]);
            float s = v0 + v1;
#pragma unroll
            for (int o = 16; o > 0; o >>= 1) s += __shfl_xor_sync(0xffffffffu, s, o);
            if (lane == 0) red[warp] = s;
            __syncthreads();
            float mu = (red[0] + red[1] + red[2] + red[3] +
                        red[4] + red[5] + red[6] + red[7]) * (1.f / 512.f);
            __syncthreads();
            float d0 = v0 - mu, d1 = v1 - mu;
            float vv = d0 * d0 + d1 * d1;
#pragma unroll
            for (int o = 16; o > 0; o >>= 1) vv += __shfl_xor_sync(0xffffffffu, vv, o);
            if (lane == 0) red[warp] = vv;
            __syncthreads();
            float var  = (red[0] + red[1] + red[2] + red[3] +
                          red[4] + red[5] + red[6] + red[7]) * (1.f / 512.f);
            float rstd = rsqrtf(var + 1e-5f);
            float y0 = d0 * rstd * lg0 + lb0;
            float y1 = d1 * rstd * lg1 + lb1;
            __stcg(&g_h[(size_t)cta * Dd + tid],       y0);
            __stcg(&g_h[(size_t)cta * Dd + tid + 256], y1);
            if (t > 0) {
                g_H[((size_t)(t - 1) * Bn + cta) * Dd + tid]       = y0;
                g_H[((size_t)(t - 1) * Bn + cta) * Dd + tid + 256] = y1;
            }
            __syncthreads();
        }
        grid_barrier(mybar, target);
    }
#undef GXLOAD
#undef LOADQ
#undef STOREQ
}

// ---------------- Gx GEMM, bf16x3 + ldmatrix + double buffer (R16) -----------
#define GXA_HI 0
#define GXA_LO 6144
#define GXB_HI 12288
#define GXB_LO 15360
#define GX_STR 48
#define GX_BUF 18432
__global__ void __launch_bounds__(256)
gemm_gx_bf16(const float* __restrict__ A, int M, int lda,
             const float* __restrict__ Bm, int N, int ldb, int K,
             const float* __restrict__ bias1, const float* __restrict__ bias2,
             float* __restrict__ C, int ldc)
{
    __shared__ __align__(16) char gs[2 * GX_BUF];
    const unsigned sb = (unsigned)__cvta_generic_to_shared(gs);

    const int tid  = threadIdx.x;
    const int lane = tid & 31;
    const int warp = tid >> 5;
    const int wn = warp & 1, wm = warp >> 1;   // 4x2 warps
    const int gid = lane >> 2, t4 = lane & 3;
    const int m0 = blockIdx.x * 128;
    const int n0 = blockIdx.y * 64;

    float acc[2][4][4];
#pragma unroll
    for (int i = 0; i < 2; i++)
#pragma unroll
        for (int j = 0; j < 4; j++)
#pragma unroll
            for (int q = 0; q < 4; q++) acc[i][j][q] = 0.f;

    float4 ra[2], rb;
    const int arow = tid >> 2, acb = tid & 3;
#define LOAD_T(K0)                                                           \
    {                                                                        \
        ra[0] = *(const float4*)(A + (size_t)(m0 + arow) * lda + (K0) + acb * 4);       \
        ra[1] = *(const float4*)(A + (size_t)(m0 + arow + 64) * lda + (K0) + acb * 4);  \
        rb    = *(const float4*)(Bm + (size_t)(n0 + arow) * ldb + (K0) + acb * 4);      \
    }
#define CVT_STORE(BUF)                                                       \
    {                                                                        \
        char* gp = gs + (BUF) * GX_BUF;                                      \
        _Pragma("unroll")                                                    \
        for (int i = 0; i < 2; i++) {                                        \
            unsigned h01 = bpack(ra[i].x, ra[i].y);                          \
            unsigned h23 = bpack(ra[i].z, ra[i].w);                          \
            unsigned l01 = bpack(ra[i].x - blo(h01), ra[i].y - bhi(h01));    \
            unsigned l23 = bpack(ra[i].z - blo(h23), ra[i].w - bhi(h23));    \
            unsigned off = (arow + i * 64) * GX_STR + acb * 8;               \
            *(uint2*)(gp + GXA_HI + off) = make_uint2(h01, h23);             \
            *(uint2*)(gp + GXA_LO + off) = make_uint2(l01, l23);             \
        }                                                                    \
        {                                                                    \
            unsigned h01 = bpack(rb.x, rb.y);                                \
            unsigned h23 = bpack(rb.z, rb.w);                                \
            unsigned l01 = bpack(rb.x - blo(h01), rb.y - bhi(h01));          \
            unsigned l23 = bpack(rb.z - blo(h23), rb.w - bhi(h23));          \
            unsigned off = arow * GX_STR + acb * 8;                          \
            *(uint2*)(gp + GXB_HI + off) = make_uint2(h01, h23);             \
            *(uint2*)(gp + GXB_LO + off) = make_uint2(l01, l23);             \
        }                                                                    \
    }

    const int sel = lane >> 3, lr = lane & 7;
    const unsigned aBase = sb + GXA_HI
        + (unsigned)((wm * 32 + (sel & 1) * 8 + lr) * GX_STR + (sel >> 1) * 16);
    const unsigned bBase = sb + GXB_HI
        + (unsigned)((wn * 32 + (sel >> 1) * 8 + lr) * GX_STR + (sel & 1) * 16);

    LOAD_T(0)
    CVT_STORE(0)
    LOAD_T(16)
    __syncthreads();

    const int NT = K / 16;      // 32 k-tiles
#pragma unroll 1
    for (int it = 0; it < NT; it++) {
        const unsigned bufo = (unsigned)(it & 1) * GX_BUF;

        unsigned bhf[2][4], blf[2][4];
#pragma unroll
        for (int nf2 = 0; nf2 < 2; nf2++) {
            ldsm4(bhf[nf2][0], bhf[nf2][1], bhf[nf2][2], bhf[nf2][3],
                  bBase + bufo + nf2 * 16 * GX_STR);
            ldsm4(blf[nf2][0], blf[nf2][1], blf[nf2][2], blf[nf2][3],
                  bBase + bufo + (GXB_LO - GXB_HI) + nf2 * 16 * GX_STR);
        }
#pragma unroll
        for (int mf = 0; mf < 2; mf++) {
            unsigned ah0, ah1, ah2, ah3, al0, al1, al2, al3;
            ldsm4(ah0, ah1, ah2, ah3, aBase + bufo + mf * 16 * GX_STR);
            ldsm4(al0, al1, al2, al3, aBase + bufo + (GXA_LO - GXA_HI) + mf * 16 * GX_STR);
#pragma unroll
            for (int nf2 = 0; nf2 < 2; nf2++) {
                mma_bf16(acc[mf][nf2 * 2    ], ah0, ah1, ah2, ah3, bhf[nf2][0], bhf[nf2][1]);
                mma_bf16(acc[mf][nf2 * 2    ], al0, al1, al2, al3, bhf[nf2][0], bhf[nf2][1]);
                mma_bf16(acc[mf][nf2 * 2    ], ah0, ah1, ah2, ah3, blf[nf2][0], blf[nf2][1]);
                mma_bf16(acc[mf][nf2 * 2 + 1], ah0, ah1, ah2, ah3, bhf[nf2][2], bhf[nf2][3]);
                mma_bf16(acc[mf][nf2 * 2 + 1], al0, al1, al2, al3, bhf[nf2][2], bhf[nf2][3]);
                mma_bf16(acc[mf][nf2 * 2 + 1], ah0, ah1, ah2, ah3, blf[nf2][2], blf[nf2][3]);
            }
        }
        if (it < NT - 1) {
            CVT_STORE((it + 1) & 1)
            if (it < NT - 2) LOAD_T((it + 2) * 16)
        }
        __syncthreads();
    }

#pragma unroll
    for (int mf = 0; mf < 2; mf++)
#pragma unroll
        for (int nf = 0; nf < 4; nf++) {
            int r0 = m0 + wm * 32 + mf * 16 + gid;
            int c0 = n0 + wn * 32 + nf * 8 + 2 * t4;
#pragma unroll
            for (int q = 0; q < 4; q++) {
                int r = r0 + ((q >= 2) ? 8 : 0);
                int c = c0 + (q & 1);
                C[(size_t)r * ldc + c] = acc[mf][nf][q] + bias1[c] + bias2[c];
            }
        }
#undef LOAD_T
#undef CVT_STORE
}

// ---------------- FC GEMM (tf32, PAD=8) + double buffer (R16) -----------------
template<int BM, int BN, int WM, int WN>
__global__ void __launch_bounds__(WM * WN * 32)
gemm_fc(const float* __restrict__ A, int M, int lda,
        const float* __restrict__ Bm, int N, int ldb, int K,
        const float* __restrict__ bias1,
        float* __restrict__ C, int ldc)
{
    constexpr int THREADS = WM * WN * 32;
    constexpr int PAD = 8;
    constexpr int MF = 2, NF = 4;

    __shared__ unsigned Ash[2][16][BM + PAD];
    __shared__ unsigned Bsh[2][16][BN + PAD];

    const int tid  = threadIdx.x;
    const int lane = tid & 31;
    const int warp = tid >> 5;
    const int wn = warp % WN, wm = warp / WN;
    const int gid = lane >> 2, t4 = lane & 3;
    const int m0 = blockIdx.x * BM;
    const int n0 = blockIdx.y * BN;

    float acc[MF][NF][4];
#pragma unroll
    for (int i = 0; i < MF; i++)
#pragma unroll
        for (int j = 0; j < NF; j++)
#pragma unroll
            for (int q = 0; q < 4; q++) acc[i][j][q] = 0.f;

    constexpr int LA = (BM * 16) / (THREADS * 4);
    constexpr int LB = (BN * 16) / (THREADS * 4);

    float4 ra[LA], rb[LB];

#define LOAD_T(K0)                                                          \
    {                                                                       \
        _Pragma("unroll")                                                   \
        for (int i = 0; i < LA; i++) {                                      \
            int f4 = tid + i * THREADS;                                     \
            int row = f4 >> 2, cb = f4 & 3;                                 \
            int gm = m0 + row;                                              \
            ra[i] = make_float4(0.f, 0.f, 0.f, 0.f);                        \
            if (gm < M) ra[i] = *(const float4*)(A + (size_t)gm * lda + (K0) + cb * 4); \
        }                                                                   \
        _Pragma("unroll")                                                   \
        for (int i = 0; i < LB; i++) {                                      \
            int f4 = tid + i * THREADS;                                     \
            int row = f4 >> 2, cb = f4 & 3;                                 \
            int grow = n0 + row;                                            \
            rb[i] = make_float4(0.f, 0.f, 0.f, 0.f);                        \
            if (grow < N) rb[i] = *(const float4*)(Bm + (size_t)grow * ldb + (K0) + cb * 4); \
        }                                                                   \
    }
#define CVT_STORE(BUF)                                                      \
    {                                                                       \
        _Pragma("unroll")                                                   \
        for (int i = 0; i < LA; i++) {                                      \
            int f4 = tid + i * THREADS;                                     \
            int row = f4 >> 2, cb = f4 & 3;                                 \
            Ash[BUF][cb * 4 + 0][row] = f2t(ra[i].x);                       \
            Ash[BUF][cb * 4 + 1][row] = f2t(ra[i].y);                       \
            Ash[BUF][cb * 4 + 2][row] = f2t(ra[i].z);                       \
            Ash[BUF][cb * 4 + 3][row] = f2t(ra[i].w);                       \
        }                                                                   \
        _Pragma("unroll")                                                   \
        for (int i = 0; i < LB; i++) {                                      \
            int f4 = tid + i * THREADS;                                     \
            int row = f4 >> 2, cb = f4 & 3;                                 \
            Bsh[BUF][cb * 4 + 0][row] = f2t(rb[i].x);                       \
            Bsh[BUF][cb * 4 + 1][row] = f2t(rb[i].y);                       \
            Bsh[BUF][cb * 4 + 2][row] = f2t(rb[i].z);                       \
            Bsh[BUF][cb * 4 + 3][row] = f2t(rb[i].w);                       \
        }                                                                   \
    }

    LOAD_T(0)
    CVT_STORE(0)
    LOAD_T(16)
    __syncthreads();

    const int NT = K / 16;
#pragma unroll 1
    for (int it = 0; it < NT; it++) {
        const int cur = it & 1;
#pragma unroll
        for (int ks = 0; ks < 2; ks++) {
            const int kb = ks * 8;
            unsigned ah[MF][4], bh[NF][2];
#pragma unroll
            for (int mf = 0; mf < MF; mf++) {
                int mm = wm * 32 + mf * 16 + gid;
                ah[mf][0] = Ash[cur][kb + t4    ][mm];
                ah[mf][1] = Ash[cur][kb + t4    ][mm + 8];
                ah[mf][2] = Ash[cur][kb + t4 + 4][mm];
                ah[mf][3] = Ash[cur][kb + t4 + 4][mm + 8];
            }
#pragma unroll
            for (int nf = 0; nf < NF; nf++) {
                int nn = wn * 32 + nf * 8 + gid;
                bh[nf][0] = Bsh[cur][kb + t4    ][nn];
                bh[nf][1] = Bsh[cur][kb + t4 + 4][nn];
            }
#pragma unroll
            for (int mf = 0; mf < MF; mf++)
#pragma unroll
                for (int nf = 0; nf < NF; nf++)
                    mma_tf32(acc[mf][nf], ah[mf], bh[nf]);
        }
        if (it < NT - 1) {
            CVT_STORE(cur ^ 1)
            if (it < NT - 2) LOAD_T((it + 2) * 16)
        }
        __syncthreads();
    }

#pragma unroll
    for (int mf = 0; mf < MF; mf++)
#pragma unroll
        for (int nf = 0; nf < NF; nf++) {
            int r0 = m0 + wm * 32 + mf * 16 + gid;
            int c0 = n0 + wn * 32 + nf * 8 + 2 * t4;
#pragma unroll
            for (int q = 0; q < 4; q++) {
                int r = r0 + ((q >= 2) ? 8 : 0);
                int c = c0 + (q & 1);
                if (r < M && c < N) {
                    int orow = (r & 127) * Ll + (r >> 7);
                    C[(size_t)orow * ldc + c] = acc[mf][nf][q] + bias1[c];
                }
            }
        }
#undef LOAD_T
#undef CVT_STORE
}

// ---------------- in-place log_softmax, rows of 10000, 512 threads -----------
__global__ void k_lsm(float* __restrict__ out) {
    __shared__ float row[Vv];
    __shared__ float red[16];
    float* p = out + (size_t)blockIdx.x * Vv;
    int tid = threadIdx.x;            // 512 threads

    float mx = -1e30f;
    float4*       r4 = (float4*)row;
    const float4* p4 = (const float4*)p;
    for (int i = tid; i < Vv / 4; i += 512) {
        float4 v = p4[i];
        r4[i] = v;
        mx = fmaxf(mx, fmaxf(fmaxf(v.x, v.y), fmaxf(v.z, v.w)));
    }
#pragma unroll
    for (int o = 16; o > 0; o >>= 1) mx = fmaxf(mx, __shfl_xor_sync(0xffffffffu, mx, o));
    if ((tid & 31) == 0) red[tid >> 5] = mx;
    __syncthreads();
    mx = red[0];
#pragma unroll
    for (int i = 1; i < 16; i++) mx = fmaxf(mx, red[i]);

    float s = 0.f;
    for (int i = tid; i < Vv; i += 512) s += expf(row[i] - mx);
#pragma unroll
    for (int o = 16; o > 0; o >>= 1) s += __shfl_xor_sync(0xffffffffu, s, o);
    __syncthreads();
    if ((tid & 31) == 0) red[tid >> 5] = s;
    __syncthreads();
    s = 0.f;
#pragma unroll
    for (int i = 0; i < 16; i++) s += red[i];
    float lse = mx + logf(s);

    for (int i = tid; i < Vv; i += 512) p[i] = row[i] - lse;
}

// ---------------- host launcher ----------------------------------------------
extern "C" void kernel_launch(void* const* d_in, const int* in_sizes, int n_in,
                              void* d_out, int out_size) {
    const float* features = (const float*)d_in[0];
    const void*  caption  = d_in[1];
    const float* embW     = (const float*)d_in[2];
    const float* Wih      = (const float*)d_in[3];
    const float* Whh      = (const float*)d_in[4];
    const float* bih      = (const float*)d_in[5];
    const float* bhh      = (const float*)d_in[6];
    const float* lng      = (const float*)d_in[7];
    const float* lnb      = (const float*)d_in[8];
    const float* fcW      = (const float*)d_in[9];
    const float* fcb      = (const float*)d_in[10];
    float*       out      = (float*)d_out;

    float *pX, *pGx, *pH;
    cudaGetSymbolAddress((void**)&pX,  g_X);
    cudaGetSymbolAddress((void**)&pGx, g_Gx);
    cudaGetSymbolAddress((void**)&pH,  g_H);

    cudaFuncSetAttribute(k_recurrence,
                         cudaFuncAttributeMaxDynamicSharedMemorySize, SMEM_REC);

    k_init<<<256, 256>>>();
    k_detect<<<1, 256>>>((const int*)caption);
    k_build_x<<<Tt * Bn, 128>>>(features, caption, embW);

    // Gx = X @ Wih^T + bih + bhh   (both layers, bf16x3 + ldmatrix, dbl-buf)
    for (int l = 0; l < 2; l++)
        gemm_gx_bf16<<<dim3(33, 32), 256>>>(
            pX, Tt * Bn, Dd,
            Wih + (size_t)l * G4 * Dd, G4, Dd, Dd,
            bih + l * G4, bhh + l * G4,
            pGx + (size_t)l * Tt * Bn * G4, G4);

    // full 33-step recurrence in ONE persistent kernel (single wave)
    k_recurrence<<<128, 256, SMEM_REC>>>(Whh, lng, lnb);

    // FC: logits = H @ fcW^T + fcb  (single tf32, permuted store, dbl-buf)
    gemm_fc<128, 64, 4, 2><<<dim3(32, 157), 256>>>(
        pH, Ll * Bn, Dd, fcW, Vv, Dd, Dd,
        fcb, out, Vv);

    k_lsm<<<Ll * Bn, 512>>>(out);
}